// round 16
// baseline (speedup 1.0000x reference)
#include <cuda_runtime.h>
#include <cuda_fp16.h>
#include <cstdint>

#define BATCH 2048
#define SEQ   64
#define DIN   512
#define HID   1024
#define CIN   1536
#define WSZ   (HID*CIN)

#define BM 128
#define BN 64          // per gate
#define BK 64
#define THREADS 256

// rows have 128B of data on a 144B pitch (odd 16B-granule multiplier -> conflict-free ldmatrix)
#define PITCH 144
#define A_TILE  (128*PITCH)          // 18432 B (single fp16)
#define B_TILE  (64*PITCH)           // 9216 B  (one gate, single fp16)
#define OFF_A   0
#define OFF_B   A_TILE               // B[g], g=0..2
#define STAGE   (A_TILE + 3*B_TILE)  // 46080 B
#define FILL_BYTES 40960             // 320 rows x 128 B per chunk
#define MBAR_OFF  768                // after 192 bias floats
#define TILES_OFF 1024
#define SMEM_DYN (TILES_OFF + 2*STAGE)  // 93184 B

// ---------------- device globals ----------------
__device__ __half g_x[(size_t)BATCH * SEQ * DIN];
__device__ __half g_w[3 * WSZ];
__device__ __half g_h[2][BATCH * HID];

// ---------------- asm helpers ----------------
__device__ __forceinline__ uint32_t smem_u32(const void* p) {
    uint32_t a;
    asm("{ .reg .u64 t; cvta.to.shared.u64 t, %1; cvt.u32.u64 %0, t; }" : "=r"(a) : "l"(p));
    return a;
}
__device__ __forceinline__ void mbar_init(uint32_t mbar, uint32_t cnt) {
    asm volatile("mbarrier.init.shared.b64 [%0], %1;" :: "r"(mbar), "r"(cnt) : "memory");
}
__device__ __forceinline__ void mbar_expect(uint32_t mbar, uint32_t bytes) {
    asm volatile("mbarrier.arrive.expect_tx.shared.b64 _, [%0], %1;"
                 :: "r"(mbar), "r"(bytes) : "memory");
}
__device__ __forceinline__ void mbar_wait(uint32_t mbar, uint32_t parity) {
    uint32_t done;
    asm volatile(
        "{\n\t.reg .pred p;\n\t"
        "mbarrier.try_wait.parity.acquire.cta.shared::cta.b64 p, [%1], %2;\n\t"
        "selp.b32 %0, 1, 0, p;\n\t}"
        : "=r"(done) : "r"(mbar), "r"(parity) : "memory");
    while (!done) {
        asm volatile(
            "{\n\t.reg .pred p;\n\t"
            "mbarrier.try_wait.parity.acquire.cta.shared::cta.b64 p, [%1], %2, 0x989680;\n\t"
            "selp.b32 %0, 1, 0, p;\n\t}"
            : "=r"(done) : "r"(mbar), "r"(parity) : "memory");
    }
}
__device__ __forceinline__ void bulk128(uint32_t dst, const void* src, uint32_t mbar) {
    asm volatile(
        "cp.async.bulk.shared::cluster.global.mbarrier::complete_tx::bytes [%0], [%1], %2, [%3];"
        :: "r"(dst), "l"(src), "r"(128u), "r"(mbar) : "memory");
}
__device__ __forceinline__ void ldmx4(uint32_t* r, uint32_t addr) {
    asm volatile("ldmatrix.sync.aligned.m8n8.x4.shared.b16 {%0,%1,%2,%3}, [%4];"
                 : "=r"(r[0]), "=r"(r[1]), "=r"(r[2]), "=r"(r[3]) : "r"(addr));
}
__device__ __forceinline__ void mma16816(float* c, const uint32_t* a,
                                         uint32_t b0, uint32_t b1) {
    asm volatile(
        "mma.sync.aligned.m16n8k16.row.col.f32.f16.f16.f32 "
        "{%0,%1,%2,%3}, {%4,%5,%6,%7}, {%8,%9}, {%0,%1,%2,%3};"
        : "+f"(c[0]), "+f"(c[1]), "+f"(c[2]), "+f"(c[3])
        : "r"(a[0]), "r"(a[1]), "r"(a[2]), "r"(a[3]), "r"(b0), "r"(b1));
}

// ---------------- convert kernels ----------------
__global__ __launch_bounds__(256)
void conv_x_kernel(const float* __restrict__ src) {
    size_t i8 = ((size_t)blockIdx.x * 256 + threadIdx.x) * 8;
    const float4* s = (const float4*)(src + i8);
    float f[8];
    *(float4*)(f + 0) = s[0];
    *(float4*)(f + 4) = s[1];
    __half h[8];
#pragma unroll
    for (int i = 0; i < 8; i++) h[i] = __float2half(f[i]);
    *(uint4*)(g_x + i8) = *(const uint4*)h;
}

__global__ __launch_bounds__(256)
void conv_w_kernel(const float* __restrict__ wf, const float* __restrict__ wg,
                   const float* __restrict__ wh) {
    size_t i8 = ((size_t)blockIdx.x * 256 + threadIdx.x) * 8;
    int gate = (int)(i8 / WSZ);
    size_t off = i8 - (size_t)gate * WSZ;
    const float* src = (gate == 0) ? wf : (gate == 1) ? wg : wh;
    const float4* s = (const float4*)(src + off);
    float f[8];
    *(float4*)(f + 0) = s[0];
    *(float4*)(f + 4) = s[1];
    __half h[8];
#pragma unroll
    for (int i = 0; i < 8; i++) h[i] = __float2half(f[i]);
    *(uint4*)(g_w + i8) = *(const uint4*)h;
}

// ---------------- step kernel ----------------
extern __shared__ char s_raw[];

__global__ __launch_bounds__(THREADS, 1)
void lnn_step(const float* __restrict__ bf, const float* __restrict__ bg,
              const float* __restrict__ bh, int t, int dst, int nchunks)
{
    const int tid  = threadIdx.x;
    const int wid  = tid >> 5;
    const int lane = tid & 31;
    const int wm   = wid & 3;      // 0..3  (M)
    const int wn   = wid >> 2;     // 0..1  (N)
    const int m0   = blockIdx.x * BM;
    const int n0   = blockIdx.y * BN;

    const __half* hin = g_h[dst ^ 1];

    const uint32_t sbase = smem_u32(s_raw);
    const uint32_t tiles = sbase + TILES_OFF;

    float* sb = (float*)s_raw;                      // sb[3][64]
    if (tid < 192) {
        int g = tid >> 6, j = tid & 63;
        const float* b = (g == 0) ? bf : (g == 1) ? bg : bh;
        sb[tid] = b[n0 + j];
    }
    if (tid == 0) {
        mbar_init(sbase + MBAR_OFF + 0, 1);
        mbar_init(sbase + MBAR_OFF + 8, 1);
    }
    __syncthreads();

    // ---- TMA bulk fill: 320 x 128B row copies per chunk ----
    auto fill = [&](int buf, int k0) {
        const uint32_t stg  = tiles + buf * STAGE;
        const uint32_t mbar = sbase + MBAR_OFF + buf * 8;
        if (tid == 0) mbar_expect(mbar, FILL_BYTES);
        const bool inx = (k0 < DIN);
        if (tid < 128) {                    // A rows
            const int r = tid;
            const __half* s = inx
                ? g_x + (size_t)(m0 + r) * (SEQ * DIN) + (size_t)t * DIN + k0
                : hin + (size_t)(m0 + r) * HID + (k0 - DIN);
            bulk128(stg + OFF_A + r * PITCH, s, mbar);
        } else {                            // B rows, gates 0-1
            const int j = tid - 128, g = j >> 6, r = j & 63;
            const __half* s = g_w + (size_t)g * WSZ + (size_t)(n0 + r) * CIN + k0;
            bulk128(stg + OFF_B + g * B_TILE + r * PITCH, s, mbar);
        }
        if (tid < 64) {                     // B rows, gate 2
            const int r = tid;
            const __half* s = g_w + (size_t)2 * WSZ + (size_t)(n0 + r) * CIN + k0;
            bulk128(stg + OFF_B + 2 * B_TILE + r * PITCH, s, mbar);
        }
    };

    float acc[3][2][4][4];
#pragma unroll
    for (int g = 0; g < 3; g++)
#pragma unroll
        for (int mt = 0; mt < 2; mt++)
#pragma unroll
            for (int nt = 0; nt < 4; nt++)
#pragma unroll
                for (int r = 0; r < 4; r++) acc[g][mt][nt][r] = 0.f;

    // per-thread ldmatrix base offsets
    const uint32_t aoff = (uint32_t)((wm * 32 + (lane & 15)) * PITCH + (lane >> 4) * 16);
    const uint32_t boff = (uint32_t)((wn * 32 + (lane & 7) + ((lane >> 4) << 3)) * PITCH
                                     + ((lane >> 3) & 1) * 16);

    // fragment buffers: A and gate-0 B double-buffered across k16; B1/B2 single
    uint32_t afr[2][2][4];                  // [buf][mt][4]
    uint32_t b0[2][2][4];                   // [buf][nt2][4]
    uint32_t b1[2][4], b2[2][4];

    auto prodA = [&](int g, uint32_t a[2][4], uint32_t b[2][4]) {
#pragma unroll
        for (int mt = 0; mt < 2; mt++)
#pragma unroll
            for (int nt = 0; nt < 4; nt++) {
                const int n2 = nt >> 1, br = (nt & 1) * 2;
                mma16816(acc[g][mt][nt], a[mt], b[n2][br], b[n2][br + 1]);
            }
    };

    uint32_t ph[2] = {0, 0};
    fill(0, 0);
    for (int ch = 0; ch < nchunks; ch++) {
        const int cur = ch & 1;
        mbar_wait(sbase + MBAR_OFF + cur * 8, ph[cur]);
        ph[cur] ^= 1;
        __syncthreads();                 // all compute on the other buffer done before refill
        if (ch + 1 < nchunks) fill(cur ^ 1, (ch + 1) * BK);

        const uint32_t stg = tiles + cur * STAGE;

        // prologue for k16 = 0
#pragma unroll
        for (int mt = 0; mt < 2; mt++)
            ldmx4(afr[0][mt], stg + OFF_A + mt * (16 * PITCH) + aoff);
        {
            uint32_t bb = stg + OFF_B + boff;
            ldmx4(b0[0][0], bb);
            ldmx4(b0[0][1], bb + 16 * PITCH);
        }

#pragma unroll
        for (int k16 = 0; k16 < 4; k16++) {
            const int kcur = k16 & 1, knxt = kcur ^ 1;
            const uint32_t kb  = k16 * 32;
            const uint32_t kbn = kb + 32;

            // gate 0 (B0 from regs), interleave B1 loads
            prodA(0, afr[kcur], b0[kcur]);
            {
                uint32_t bb = stg + OFF_B + 1 * B_TILE + kb + boff;
                ldmx4(b1[0], bb);
                ldmx4(b1[1], bb + 16 * PITCH);
            }

            // gate 1, interleave B2 + next-A loads
            prodA(1, afr[kcur], b1);
            {
                uint32_t bb = stg + OFF_B + 2 * B_TILE + kb + boff;
                ldmx4(b2[0], bb);
                ldmx4(b2[1], bb + 16 * PITCH);
            }
            if (k16 < 3) {
#pragma unroll
                for (int mt = 0; mt < 2; mt++)
                    ldmx4(afr[knxt][mt], stg + OFF_A + mt * (16 * PITCH) + kbn + aoff);
            }

            // gate 2, interleave next-B0 loads
            prodA(2, afr[kcur], b2);
            if (k16 < 3) {
                uint32_t bb = stg + OFF_B + kbn + boff;
                ldmx4(b0[knxt][0], bb);
                ldmx4(b0[knxt][1], bb + 16 * PITCH);
            }
        }
    }

    // ---- epilogue: bias + sigmoid gate, write h (single fp16) ----
    __half* hout = g_h[dst];
#pragma unroll
    for (int mt = 0; mt < 2; mt++)
#pragma unroll
        for (int nt = 0; nt < 4; nt++)
#pragma unroll
            for (int rh = 0; rh < 2; rh++) {
                const int row  = m0 + wm * 32 + mt * 16 + (lane >> 2) + rh * 8;
                const int colb = wn * 32 + nt * 8 + (lane & 3) * 2;   // block-local
                __half v[2];
#pragma unroll
                for (int q = 0; q < 2; q++) {
                    const float fo = acc[0][mt][nt][2 * rh + q] + sb[colb + q];
                    const float go = acc[1][mt][nt][2 * rh + q] + sb[64 + colb + q];
                    const float ho = acc[2][mt][nt][2 * rh + q] + sb[128 + colb + q];
                    const float gate = 1.0f / (1.0f + __expf(fo));    // sigmoid(-f)
                    v[q] = __float2half(gate * go + (1.0f - gate) * ho);
                }
                *(uint32_t*)(hout + (size_t)row * HID + n0 + colb) = *(const uint32_t*)v;
            }
}

// ---------------- FC head ----------------
__global__ __launch_bounds__(256)
void lnn_fc(const float* __restrict__ Wfc, const float* __restrict__ bfc,
            float* __restrict__ out, int src)
{
    const int b = blockIdx.x * blockDim.x + threadIdx.x;
    if (b >= BATCH) return;
    const __half* h = g_h[src] + (size_t)b * HID;
    const float* w0 = Wfc;
    const float* w1 = Wfc + HID;
    float s0 = 0.f, s1 = 0.f;
#pragma unroll 8
    for (int i = 0; i < HID; i++) {
        float hv = __half2float(h[i]);
        s0 += hv * w0[i];
        s1 += hv * w1[i];
    }
    out[b * 2 + 0] = s0 + bfc[0];
    out[b * 2 + 1] = s1 + bfc[1];
}

// ---------------- launch ----------------
extern "C" void kernel_launch(void* const* d_in, const int* in_sizes, int n_in,
                              void* d_out, int out_size)
{
    const float* x   = (const float*)d_in[0];
    const float* Wf  = (const float*)d_in[1];
    const float* bf  = (const float*)d_in[2];
    const float* Wg  = (const float*)d_in[3];
    const float* bg  = (const float*)d_in[4];
    const float* Wh  = (const float*)d_in[5];
    const float* bh  = (const float*)d_in[6];
    const float* Wfc = (const float*)d_in[7];
    const float* bfc = (const float*)d_in[8];
    float* out = (float*)d_out;

    cudaFuncSetAttribute(lnn_step, cudaFuncAttributeMaxDynamicSharedMemorySize, SMEM_DYN);

    conv_x_kernel<<<(BATCH * SEQ * DIN) / 2048, 256>>>(x);
    conv_w_kernel<<<(3 * WSZ) / 2048, 256>>>(Wf, Wg, Wh);

    dim3 grid(BATCH / BM, HID / BN);   // 16 x 16 = 256 CTAs
    for (int t = 0; t < SEQ; t++) {
        lnn_step<<<grid, THREADS, SMEM_DYN>>>(bf, bg, bh, t, t & 1,
                                              (t == 0) ? (DIN / BK) : (CIN / BK));
    }
    lnn_fc<<<BATCH / 256, 256>>>(Wfc, bfc, out, 1);
}